// round 1
// baseline (speedup 1.0000x reference)
#include <cuda_runtime.h>
#include <cuda_bf16.h>
#include <math.h>

// Problem constants
#define B_  8
#define C_  256
#define T_  32
#define HW_ 784            // 28*28
#define HW4_ 196           // HW/4
#define HID_ 512
#define EMB_ 32
#define NBINS_ 4
#define SCALE_ 5.0f

// Scratch (device globals — no allocation allowed)
__device__ float g_pooled[B_ * C_ * T_];   // [B,C,T]
__device__ float g_h[B_ * HID_ * T_];      // [B,HID,T]
__device__ float g_nw[B_ * T_ * NBINS_];   // [B,T,4] packed so float4 @ (b*32+t)

// ---------------------------------------------------------------------------
// Kernel 1: spatial mean pool.  One warp per (b,c,t) row of 784 floats.
// ---------------------------------------------------------------------------
__global__ void pool_kernel(const float* __restrict__ x) {
    int warp = (blockIdx.x * blockDim.x + threadIdx.x) >> 5;
    int lane = threadIdx.x & 31;
    if (warp >= B_ * C_ * T_) return;
    const float4* row = reinterpret_cast<const float4*>(x) + (size_t)warp * HW4_;
    float s = 0.0f;
#pragma unroll
    for (int i = 0; i < 7; i++) {
        int idx = lane + i * 32;
        if (idx < HW4_) {
            float4 v = row[idx];
            s += (v.x + v.y) + (v.z + v.w);
        }
    }
#pragma unroll
    for (int o = 16; o > 0; o >>= 1) s += __shfl_xor_sync(0xFFFFFFFFu, s, o);
    if (lane == 0) g_pooled[warp] = s * (1.0f / (float)HW_);
}

// ---------------------------------------------------------------------------
// Kernel 2a: h = hswish(W1 @ pooled + b1).  One warp per (b,hid), lane = t.
// ---------------------------------------------------------------------------
__global__ void mlp1_kernel(const float* __restrict__ W1, const float* __restrict__ b1) {
    int warp = (blockIdx.x * blockDim.x + threadIdx.x) >> 5;
    int lane = threadIdx.x & 31;  // t
    if (warp >= B_ * HID_) return;
    int b = warp >> 9;            // /512
    int hid = warp & (HID_ - 1);
    const float* pb = g_pooled + (size_t)b * C_ * T_;
    const float* w = W1 + (size_t)hid * C_;
    float acc = b1[hid];
#pragma unroll 8
    for (int c = 0; c < C_; c++) {
        acc = fmaf(__ldg(w + c), pb[c * T_ + lane], acc);
    }
    // hswish: x * clip(x+3, 0, 6) / 6
    float g = fminf(fmaxf(acc + 3.0f, 0.0f), 6.0f);
    acc = acc * g * (1.0f / 6.0f);
    g_h[((size_t)b * HID_ + hid) * T_ + lane] = acc;
}

// ---------------------------------------------------------------------------
// Kernel 2b: per-batch block (1024 threads): embds, l2norm, adjacent sims,
// 3rd-smallest threshold, grouping, centers, softmax -> norm_weights.
// ---------------------------------------------------------------------------
__global__ __launch_bounds__(1024, 1)
void weights_kernel(const float* __restrict__ W2, const float* __restrict__ b2) {
    __shared__ float ne[EMB_][T_ + 1];   // normalized embds [e][t]
    __shared__ float invn[T_];
    __shared__ float nsv[T_];            // ns[0..30]
    __shared__ float thresh;
    __shared__ int   grp[T_];
    __shared__ float csum[EMB_][NBINS_];
    __shared__ float gsize[NBINS_];
    __shared__ float ncen[EMB_][NBINS_];
    __shared__ float wts[T_][NBINS_];
    __shared__ float sscale[NBINS_];

    int b = blockIdx.x;
    int tid = threadIdx.x;
    int e = tid >> 5;
    int t = tid & 31;

    // embds[e][t] = b2[e] + sum_hh W2[e,hh] * h[b,hh,t]
    {
        const float* hb = g_h + (size_t)b * HID_ * T_;
        const float* w2r = W2 + (size_t)e * HID_;
        float acc = b2[e];
#pragma unroll 8
        for (int hh = 0; hh < HID_; hh++) {
            acc = fmaf(__ldg(w2r + hh), hb[hh * T_ + t], acc);
        }
        ne[e][t] = acc;
    }
    __syncthreads();

    // l2norm over e (axis=1)
    if (tid < T_) {
        float s = 0.0f;
        for (int ee = 0; ee < EMB_; ee++) { float v = ne[ee][tid]; s += v * v; }
        invn[tid] = 1.0f / fmaxf(sqrtf(s), 1e-12f);
    }
    __syncthreads();
    ne[e][t] *= invn[t];
    __syncthreads();

    // ns[t] = dot(ne[:,t+1], ne[:,t]), t=0..30
    if (tid < T_ - 1) {
        float s = 0.0f;
        for (int ee = 0; ee < EMB_; ee++) s += ne[ee][tid + 1] * ne[ee][tid];
        nsv[tid] = s;
    }
    __syncthreads();

    // threshold = 3rd smallest of ns (rank 2, tie-break by index)
    if (tid < T_ - 1) {
        float v = nsv[tid];
        int cnt = 0;
        for (int j = 0; j < T_ - 1; j++) {
            float o = nsv[j];
            cnt += (o < v) || (o == v && j < tid);
        }
        if (cnt == 2) thresh = v;
    }
    __syncthreads();

    // groups via cumsum of interval ends
    if (tid == 0) {
        int g = 0;
        grp[0] = 0;
        for (int tt = 1; tt < T_; tt++) {
            g += (nsv[tt - 1] <= thresh) ? 1 : 0;
            grp[tt] = g;
        }
    }
    __syncthreads();

    // centers_sum[e][k], group sizes
    if (tid < EMB_ * NBINS_) {
        int ee = tid >> 2, k = tid & 3;
        float s = 0.0f;
        for (int tt = 0; tt < T_; tt++) if (grp[tt] == k) s += ne[ee][tt];
        csum[ee][k] = s;
    }
    if (tid < NBINS_) {
        float s = 0.0f;
        for (int tt = 0; tt < T_; tt++) s += (grp[tt] == tid) ? 1.0f : 0.0f;
        gsize[tid] = s;
    }
    __syncthreads();

    // normalized centers per bin
    if (tid < NBINS_) {
        int k = tid;
        float gs = gsize[k];
        float inv_gs = (gs > 0.0f) ? (1.0f / gs) : 0.0f;
        float s = 0.0f;
        for (int ee = 0; ee < EMB_; ee++) { float v = csum[ee][k] * inv_gs; s += v * v; }
        float inv_n = 1.0f / fmaxf(sqrtf(s), 1e-12f);
        for (int ee = 0; ee < EMB_; ee++) ncen[ee][k] = csum[ee][k] * inv_gs * inv_n;
    }
    __syncthreads();

    // similarities + (later) softmax; sims[t][k] scaled by SCALE
    if (tid < T_ * NBINS_) {
        int tt = tid >> 2, k = tid & 3;
        float s = 0.0f;
        for (int ee = 0; ee < EMB_; ee++) s += ne[ee][tt] * ncen[ee][k];
        wts[tt][k] = SCALE_ * s;   // temp storage of scaled sims
    }
    __syncthreads();

    // softmax over k per t
    if (tid < T_) {
        float s0 = wts[tid][0], s1 = wts[tid][1], s2 = wts[tid][2], s3 = wts[tid][3];
        float m = fmaxf(fmaxf(s0, s1), fmaxf(s2, s3));
        float e0 = expf(s0 - m), e1 = expf(s1 - m), e2 = expf(s2 - m), e3 = expf(s3 - m);
        float inv = 1.0f / (e0 + e1 + e2 + e3);
        wts[tid][0] = e0 * inv; wts[tid][1] = e1 * inv;
        wts[tid][2] = e2 * inv; wts[tid][3] = e3 * inv;
    }
    __syncthreads();

    // column scales: 1/sum_t weights (or 1 if sum==0)
    if (tid < NBINS_) {
        float s = 0.0f;
        for (int tt = 0; tt < T_; tt++) s += wts[tt][tid];
        sscale[tid] = (s > 0.0f) ? (1.0f / s) : 1.0f;
    }
    __syncthreads();

    if (tid < T_ * NBINS_) {
        int tt = tid >> 2, k = tid & 3;
        g_nw[(size_t)b * T_ * NBINS_ + tt * NBINS_ + k] = wts[tt][k] * sscale[k];
    }
}

// ---------------------------------------------------------------------------
// Kernel 3: out[b,c,k,p] = sum_t x[b,c,t,p] * nw[b,t,k]
// One thread per (b,c,p4) float4 position; computes all 4 bins.
// ---------------------------------------------------------------------------
__global__ __launch_bounds__(256, 8)
void output_kernel(const float* __restrict__ x, float* __restrict__ out) {
    int gtid = blockIdx.x * blockDim.x + threadIdx.x;
    const int TOTAL = B_ * C_ * HW4_;
    if (gtid >= TOTAL) return;
    int bc = gtid / HW4_;
    int p  = gtid - bc * HW4_;
    int b  = bc >> 8;  // /C_

    const float4* xr = reinterpret_cast<const float4*>(x) + (size_t)bc * T_ * HW4_ + p;
    const float4* wr = reinterpret_cast<const float4*>(g_nw) + (size_t)b * T_;

    float4 a0 = {0,0,0,0}, a1 = {0,0,0,0}, a2 = {0,0,0,0}, a3 = {0,0,0,0};
#pragma unroll
    for (int t = 0; t < T_; t++) {
        float4 v = xr[(size_t)t * HW4_];
        float4 w = __ldg(&wr[t]);
        a0.x = fmaf(v.x, w.x, a0.x); a0.y = fmaf(v.y, w.x, a0.y);
        a0.z = fmaf(v.z, w.x, a0.z); a0.w = fmaf(v.w, w.x, a0.w);
        a1.x = fmaf(v.x, w.y, a1.x); a1.y = fmaf(v.y, w.y, a1.y);
        a1.z = fmaf(v.z, w.y, a1.z); a1.w = fmaf(v.w, w.y, a1.w);
        a2.x = fmaf(v.x, w.z, a2.x); a2.y = fmaf(v.y, w.z, a2.y);
        a2.z = fmaf(v.z, w.z, a2.z); a2.w = fmaf(v.w, w.z, a2.w);
        a3.x = fmaf(v.x, w.w, a3.x); a3.y = fmaf(v.y, w.w, a3.y);
        a3.z = fmaf(v.z, w.w, a3.z); a3.w = fmaf(v.w, w.w, a3.w);
    }
    float4* o = reinterpret_cast<float4*>(out) + (size_t)bc * NBINS_ * HW4_ + p;
    o[0 * HW4_] = a0;
    o[1 * HW4_] = a1;
    o[2 * HW4_] = a2;
    o[3 * HW4_] = a3;
}

// ---------------------------------------------------------------------------
extern "C" void kernel_launch(void* const* d_in, const int* in_sizes, int n_in,
                              void* d_out, int out_size) {
    const float* x  = (const float*)d_in[0];
    const float* W1 = (const float*)d_in[1];
    const float* b1 = (const float*)d_in[2];
    const float* W2 = (const float*)d_in[3];
    const float* b2 = (const float*)d_in[4];
    float* out = (float*)d_out;

    // Pass 1: pooling (65536 warps, 8 warps/block)
    pool_kernel<<<(B_ * C_ * T_) / 8, 256>>>(x);

    // Middle: MLP layer 1 (4096 warps)
    mlp1_kernel<<<(B_ * HID_) / 8, 256>>>(W1, b1);

    // Middle: per-batch weights
    weights_kernel<<<B_, 1024>>>(W2, b2);

    // Pass 2: weighted temporal pooling
    int total = B_ * C_ * HW4_;
    output_kernel<<<(total + 255) / 256, 256>>>(x, out);
}

// round 2
// speedup vs baseline: 1.1913x; 1.1913x over previous
#include <cuda_runtime.h>
#include <cuda_bf16.h>
#include <math.h>

// Problem constants
#define B_  8
#define C_  256
#define T_  32
#define HW_ 784            // 28*28
#define HW4_ 196           // HW/4
#define HID_ 512
#define EMB_ 32
#define NBINS_ 4
#define SCALE_ 5.0f

// Scratch (device globals — no allocation allowed)
__device__ float g_pooled[B_ * C_ * T_];   // [B,C,T]
__device__ float g_h[B_ * HID_ * T_];      // [B,HID,T]
__device__ float g_nw[B_ * T_ * NBINS_];   // [B,T,4] => float4 per (b,t)

// ---------------------------------------------------------------------------
// Kernel 1: spatial mean pool.  One warp per (b,c,t) row of 784 floats.
// ---------------------------------------------------------------------------
__global__ void pool_kernel(const float* __restrict__ x) {
    int warp = (blockIdx.x * blockDim.x + threadIdx.x) >> 5;
    int lane = threadIdx.x & 31;
    if (warp >= B_ * C_ * T_) return;
    const float4* row = reinterpret_cast<const float4*>(x) + (size_t)warp * HW4_;
    // 196 = 6*32 + 4 : 6 full rounds + masked tail. Issue all loads up front.
    float4 v0 = row[lane];
    float4 v1 = row[lane + 32];
    float4 v2 = row[lane + 64];
    float4 v3 = row[lane + 96];
    float4 v4 = row[lane + 128];
    float4 v5 = row[lane + 160];
    float4 v6 = (lane < 4) ? row[lane + 192] : make_float4(0.f, 0.f, 0.f, 0.f);
    float s = (v0.x + v0.y) + (v0.z + v0.w);
    s += (v1.x + v1.y) + (v1.z + v1.w);
    s += (v2.x + v2.y) + (v2.z + v2.w);
    s += (v3.x + v3.y) + (v3.z + v3.w);
    s += (v4.x + v4.y) + (v4.z + v4.w);
    s += (v5.x + v5.y) + (v5.z + v5.w);
    s += (v6.x + v6.y) + (v6.z + v6.w);
#pragma unroll
    for (int o = 16; o > 0; o >>= 1) s += __shfl_xor_sync(0xFFFFFFFFu, s, o);
    if (lane == 0) g_pooled[warp] = s * (1.0f / (float)HW_);
}

// ---------------------------------------------------------------------------
// Kernel 2a: h = hswish(W1 @ pooled + b1).
// Block = 256 threads = 8 warps, one b per block, 8 hids per block.
// pooled[b] staged in shared (32 KB).
// ---------------------------------------------------------------------------
__global__ __launch_bounds__(256)
void mlp1_kernel(const float* __restrict__ W1, const float* __restrict__ b1) {
    __shared__ float sp[C_ * T_];   // 32 KB
    int b = blockIdx.x >> 6;                 // /64
    int hid0 = (blockIdx.x & 63) * 8;
    int tid = threadIdx.x;
    // Stage pooled[b] (8192 floats) coalesced: 8 float4 per thread
    {
        const float4* src = reinterpret_cast<const float4*>(g_pooled + (size_t)b * C_ * T_);
        float4* dst = reinterpret_cast<float4*>(sp);
#pragma unroll
        for (int i = 0; i < 8; i++) dst[tid + i * 256] = src[tid + i * 256];
    }
    __syncthreads();

    int w = tid >> 5;        // warp -> hid offset
    int lane = tid & 31;     // t
    int hid = hid0 + w;
    const float* wr = W1 + (size_t)hid * C_;
    float a0 = 0.f, a1 = 0.f, a2 = 0.f, a3 = 0.f;
#pragma unroll 8
    for (int c = 0; c < C_; c += 4) {
        a0 = fmaf(__ldg(wr + c + 0), sp[(c + 0) * T_ + lane], a0);
        a1 = fmaf(__ldg(wr + c + 1), sp[(c + 1) * T_ + lane], a1);
        a2 = fmaf(__ldg(wr + c + 2), sp[(c + 2) * T_ + lane], a2);
        a3 = fmaf(__ldg(wr + c + 3), sp[(c + 3) * T_ + lane], a3);
    }
    float acc = ((a0 + a1) + (a2 + a3)) + b1[hid];
    float g = fminf(fmaxf(acc + 3.0f, 0.0f), 6.0f);
    acc = acc * g * (1.0f / 6.0f);
    g_h[((size_t)b * HID_ + hid) * T_ + lane] = acc;
}

// ---------------------------------------------------------------------------
// Kernel 2b: per-batch block (1024 threads): embds, l2norm, adjacent sims,
// 3rd-smallest threshold, grouping, centers, softmax -> norm_weights.
// ---------------------------------------------------------------------------
__global__ __launch_bounds__(1024, 1)
void weights_kernel(const float* __restrict__ W2, const float* __restrict__ b2) {
    __shared__ float ne[EMB_][T_ + 1];   // normalized embds [e][t]
    __shared__ float invn[T_];
    __shared__ float nsv[T_];            // ns[0..30]
    __shared__ float thresh;
    __shared__ int   grp[T_];
    __shared__ float csum[EMB_][NBINS_];
    __shared__ float gsize[NBINS_];
    __shared__ float ncen[EMB_][NBINS_];
    __shared__ float wts[T_][NBINS_];
    __shared__ float sscale[NBINS_];

    int b = blockIdx.x;
    int tid = threadIdx.x;
    int e = tid >> 5;
    int t = tid & 31;

    // embds[e][t] = b2[e] + sum_hh W2[e,hh] * h[b,hh,t]  (4-way ILP)
    {
        const float* hb = g_h + (size_t)b * HID_ * T_;
        const float* w2r = W2 + (size_t)e * HID_;
        float a0 = 0.f, a1 = 0.f, a2 = 0.f, a3 = 0.f;
#pragma unroll 8
        for (int hh = 0; hh < HID_; hh += 4) {
            a0 = fmaf(__ldg(w2r + hh + 0), hb[(hh + 0) * T_ + t], a0);
            a1 = fmaf(__ldg(w2r + hh + 1), hb[(hh + 1) * T_ + t], a1);
            a2 = fmaf(__ldg(w2r + hh + 2), hb[(hh + 2) * T_ + t], a2);
            a3 = fmaf(__ldg(w2r + hh + 3), hb[(hh + 3) * T_ + t], a3);
        }
        ne[e][t] = ((a0 + a1) + (a2 + a3)) + b2[e];
    }
    __syncthreads();

    // l2norm over e (axis=1)
    if (tid < T_) {
        float s = 0.0f;
        for (int ee = 0; ee < EMB_; ee++) { float v = ne[ee][tid]; s += v * v; }
        invn[tid] = 1.0f / fmaxf(sqrtf(s), 1e-12f);
    }
    __syncthreads();
    ne[e][t] *= invn[t];
    __syncthreads();

    // ns[t] = dot(ne[:,t+1], ne[:,t]), t=0..30
    if (tid < T_ - 1) {
        float s = 0.0f;
        for (int ee = 0; ee < EMB_; ee++) s += ne[ee][tid + 1] * ne[ee][tid];
        nsv[tid] = s;
    }
    __syncthreads();

    // threshold = 3rd smallest of ns (rank 2, tie-break by index)
    if (tid < T_ - 1) {
        float v = nsv[tid];
        int cnt = 0;
        for (int j = 0; j < T_ - 1; j++) {
            float o = nsv[j];
            cnt += (o < v) || (o == v && j < tid);
        }
        if (cnt == 2) thresh = v;
    }
    __syncthreads();

    // groups via cumsum of interval ends
    if (tid == 0) {
        int g = 0;
        grp[0] = 0;
        for (int tt = 1; tt < T_; tt++) {
            g += (nsv[tt - 1] <= thresh) ? 1 : 0;
            grp[tt] = g;
        }
    }
    __syncthreads();

    // centers_sum[e][k], group sizes
    if (tid < EMB_ * NBINS_) {
        int ee = tid >> 2, k = tid & 3;
        float s = 0.0f;
        for (int tt = 0; tt < T_; tt++) if (grp[tt] == k) s += ne[ee][tt];
        csum[ee][k] = s;
    }
    if (tid < NBINS_) {
        float s = 0.0f;
        for (int tt = 0; tt < T_; tt++) s += (grp[tt] == tid) ? 1.0f : 0.0f;
        gsize[tid] = s;
    }
    __syncthreads();

    // normalized centers per bin
    if (tid < NBINS_) {
        int k = tid;
        float gs = gsize[k];
        float inv_gs = (gs > 0.0f) ? (1.0f / gs) : 0.0f;
        float s = 0.0f;
        for (int ee = 0; ee < EMB_; ee++) { float v = csum[ee][k] * inv_gs; s += v * v; }
        float inv_n = 1.0f / fmaxf(sqrtf(s), 1e-12f);
        for (int ee = 0; ee < EMB_; ee++) ncen[ee][k] = csum[ee][k] * inv_gs * inv_n;
    }
    __syncthreads();

    // similarities (scaled)
    if (tid < T_ * NBINS_) {
        int tt = tid >> 2, k = tid & 3;
        float s = 0.0f;
        for (int ee = 0; ee < EMB_; ee++) s += ne[ee][tt] * ncen[ee][k];
        wts[tt][k] = SCALE_ * s;
    }
    __syncthreads();

    // softmax over k per t
    if (tid < T_) {
        float s0 = wts[tid][0], s1 = wts[tid][1], s2 = wts[tid][2], s3 = wts[tid][3];
        float m = fmaxf(fmaxf(s0, s1), fmaxf(s2, s3));
        float e0 = expf(s0 - m), e1 = expf(s1 - m), e2 = expf(s2 - m), e3 = expf(s3 - m);
        float inv = 1.0f / (e0 + e1 + e2 + e3);
        wts[tid][0] = e0 * inv; wts[tid][1] = e1 * inv;
        wts[tid][2] = e2 * inv; wts[tid][3] = e3 * inv;
    }
    __syncthreads();

    // column scales: 1/sum_t weights (or 1 if sum==0)
    if (tid < NBINS_) {
        float s = 0.0f;
        for (int tt = 0; tt < T_; tt++) s += wts[tt][tid];
        sscale[tid] = (s > 0.0f) ? (1.0f / s) : 1.0f;
    }
    __syncthreads();

    if (tid < T_ * NBINS_) {
        int tt = tid >> 2, k = tid & 3;
        g_nw[(size_t)b * T_ * NBINS_ + tt * NBINS_ + k] = wts[tt][k] * sscale[k];
    }
}

// ---------------------------------------------------------------------------
// Kernel 3: out[b,c,k,p] = sum_t x[b,c,t,p] * nw[b,t,k]
// One thread per (b,c,p4) float4 position; computes all 4 bins.
// Weights staged in shared (all batches: 256 float4 = 4 KB).
// 64-reg budget so ptxas can keep many x-loads in flight.
// ---------------------------------------------------------------------------
__global__ __launch_bounds__(256, 4)
void output_kernel(const float* __restrict__ x, float* __restrict__ out) {
    __shared__ float4 swt[B_ * T_];   // [b][t]
    {
        const float4* src = reinterpret_cast<const float4*>(g_nw);
        swt[threadIdx.x] = src[threadIdx.x];   // 256 threads, 256 entries
    }
    __syncthreads();

    int gtid = blockIdx.x * blockDim.x + threadIdx.x;
    const int TOTAL = B_ * C_ * HW4_;
    if (gtid >= TOTAL) return;
    int bc = gtid / HW4_;
    int p  = gtid - bc * HW4_;
    int b  = bc >> 8;  // /C_

    const float4* xr = reinterpret_cast<const float4*>(x) + (size_t)bc * T_ * HW4_ + p;
    const float4* wb = swt + b * T_;

    float4 a0 = {0,0,0,0}, a1 = {0,0,0,0}, a2 = {0,0,0,0}, a3 = {0,0,0,0};
#pragma unroll
    for (int t = 0; t < T_; t++) {
        float4 v = xr[(size_t)t * HW4_];
        float4 w = wb[t];
        a0.x = fmaf(v.x, w.x, a0.x); a0.y = fmaf(v.y, w.x, a0.y);
        a0.z = fmaf(v.z, w.x, a0.z); a0.w = fmaf(v.w, w.x, a0.w);
        a1.x = fmaf(v.x, w.y, a1.x); a1.y = fmaf(v.y, w.y, a1.y);
        a1.z = fmaf(v.z, w.y, a1.z); a1.w = fmaf(v.w, w.y, a1.w);
        a2.x = fmaf(v.x, w.z, a2.x); a2.y = fmaf(v.y, w.z, a2.y);
        a2.z = fmaf(v.z, w.z, a2.z); a2.w = fmaf(v.w, w.z, a2.w);
        a3.x = fmaf(v.x, w.w, a3.x); a3.y = fmaf(v.y, w.w, a3.y);
        a3.z = fmaf(v.z, w.w, a3.z); a3.w = fmaf(v.w, w.w, a3.w);
    }
    float4* o = reinterpret_cast<float4*>(out) + (size_t)bc * NBINS_ * HW4_ + p;
    o[0 * HW4_] = a0;
    o[1 * HW4_] = a1;
    o[2 * HW4_] = a2;
    o[3 * HW4_] = a3;
}

// ---------------------------------------------------------------------------
extern "C" void kernel_launch(void* const* d_in, const int* in_sizes, int n_in,
                              void* d_out, int out_size) {
    const float* x  = (const float*)d_in[0];
    const float* W1 = (const float*)d_in[1];
    const float* b1 = (const float*)d_in[2];
    const float* W2 = (const float*)d_in[3];
    const float* b2 = (const float*)d_in[4];
    float* out = (float*)d_out;

    pool_kernel<<<(B_ * C_ * T_) / 8, 256>>>(x);
    mlp1_kernel<<<(B_ * HID_) / 8, 256>>>(W1, b1);
    weights_kernel<<<B_, 1024>>>(W2, b2);
    int total = B_ * C_ * HW4_;
    output_kernel<<<(total + 255) / 256, 256>>>(x, out);
}

// round 3
// speedup vs baseline: 1.3262x; 1.1133x over previous
#include <cuda_runtime.h>
#include <cuda_bf16.h>
#include <math.h>

// Problem constants
#define B_  8
#define C_  256
#define T_  32
#define HW_ 784            // 28*28
#define HW4_ 196           // HW/4
#define HID_ 512
#define EMB_ 32
#define NBINS_ 4
#define SCALE_ 5.0f

// Scratch (device globals — no allocation allowed)
__device__ float g_pooled[B_ * C_ * T_];   // [B,C,T]
__device__ float g_h[B_ * HID_ * T_];      // [B,HID,T]
__device__ float g_nw[B_ * T_ * NBINS_];   // [B,T,4]

// ---------------------------------------------------------------------------
// Kernel 1: spatial mean pool.  One warp per (b,c,t) row of 784 floats.
// ---------------------------------------------------------------------------
__global__ void pool_kernel(const float* __restrict__ x) {
    int warp = (blockIdx.x * blockDim.x + threadIdx.x) >> 5;
    int lane = threadIdx.x & 31;
    if (warp >= B_ * C_ * T_) return;
    const float4* row = reinterpret_cast<const float4*>(x) + (size_t)warp * HW4_;
    float4 v0 = row[lane];
    float4 v1 = row[lane + 32];
    float4 v2 = row[lane + 64];
    float4 v3 = row[lane + 96];
    float4 v4 = row[lane + 128];
    float4 v5 = row[lane + 160];
    float4 v6 = (lane < 4) ? row[lane + 192] : make_float4(0.f, 0.f, 0.f, 0.f);
    float s = (v0.x + v0.y) + (v0.z + v0.w);
    s += (v1.x + v1.y) + (v1.z + v1.w);
    s += (v2.x + v2.y) + (v2.z + v2.w);
    s += (v3.x + v3.y) + (v3.z + v3.w);
    s += (v4.x + v4.y) + (v4.z + v4.w);
    s += (v5.x + v5.y) + (v5.z + v5.w);
    s += (v6.x + v6.y) + (v6.z + v6.w);
#pragma unroll
    for (int o = 16; o > 0; o >>= 1) s += __shfl_xor_sync(0xFFFFFFFFu, s, o);
    if (lane == 0) g_pooled[warp] = s * (1.0f / (float)HW_);
}

// ---------------------------------------------------------------------------
// Kernel 2a: h = hswish(W1 @ pooled + b1).
// Block = 256 threads = 8 warps, one b per block, 8 hids per block.
// pooled[b] (32 KB) AND 8 W1 rows (8 KB) staged in shared.
// ---------------------------------------------------------------------------
__global__ __launch_bounds__(256)
void mlp1_kernel(const float* __restrict__ W1, const float* __restrict__ b1) {
    __shared__ float sp[C_ * T_];   // 32 KB
    __shared__ float sw[8 * C_];    // 8 KB
    int b = blockIdx.x >> 6;                 // /64
    int hid0 = (blockIdx.x & 63) * 8;
    int tid = threadIdx.x;
    // Stage pooled[b] (8192 floats): 8 float4/thread
    {
        const float4* src = reinterpret_cast<const float4*>(g_pooled + (size_t)b * C_ * T_);
        float4* dst = reinterpret_cast<float4*>(sp);
#pragma unroll
        for (int i = 0; i < 8; i++) dst[tid + i * 256] = src[tid + i * 256];
    }
    // Stage W1 rows hid0..hid0+7 (2048 floats contiguous): 2 float4/thread
    {
        const float4* src = reinterpret_cast<const float4*>(W1 + (size_t)hid0 * C_);
        float4* dst = reinterpret_cast<float4*>(sw);
        dst[tid] = src[tid];
        dst[tid + 256] = src[tid + 256];
    }
    __syncthreads();

    int w = tid >> 5;        // warp -> hid offset
    int lane = tid & 31;     // t
    int hid = hid0 + w;
    const float* wr = sw + w * C_;
    float a0 = 0.f, a1 = 0.f, a2 = 0.f, a3 = 0.f;
#pragma unroll 8
    for (int c = 0; c < C_; c += 4) {
        a0 = fmaf(wr[c + 0], sp[(c + 0) * T_ + lane], a0);
        a1 = fmaf(wr[c + 1], sp[(c + 1) * T_ + lane], a1);
        a2 = fmaf(wr[c + 2], sp[(c + 2) * T_ + lane], a2);
        a3 = fmaf(wr[c + 3], sp[(c + 3) * T_ + lane], a3);
    }
    float acc = ((a0 + a1) + (a2 + a3)) + b1[hid];
    float g = fminf(fmaxf(acc + 3.0f, 0.0f), 6.0f);
    acc = acc * g * (1.0f / 6.0f);
    g_h[((size_t)b * HID_ + hid) * T_ + lane] = acc;
}

// ---------------------------------------------------------------------------
// Kernel 2b: per-batch block (1024 threads).
// Stages h[b] (64 KB) + W2 (64 KB) into dynamic smem, then embds with
// 4-e register tiling (256 active threads), then grouping/softmax.
// ---------------------------------------------------------------------------
extern __shared__ float dynsm[];   // [0:16384)=h [hid][t], [16384:32768)=W2 [e][hh]

__global__ __launch_bounds__(1024, 1)
void weights_kernel(const float* __restrict__ W2, const float* __restrict__ b2) {
    __shared__ float ne[EMB_][T_ + 1];   // normalized embds [e][t]
    __shared__ float invn[T_];
    __shared__ float nsv[T_];            // ns[0..30]
    __shared__ float thresh;
    __shared__ int   grp[T_];
    __shared__ float csum[EMB_][NBINS_];
    __shared__ float gsize[NBINS_];
    __shared__ float ncen[EMB_][NBINS_];
    __shared__ float wts[T_][NBINS_];
    __shared__ float sscale[NBINS_];

    int b = blockIdx.x;
    int tid = threadIdx.x;
    float* sh  = dynsm;            // h[b]: [hid][t]
    float* sw2 = dynsm + HID_ * T_;  // W2: [e][hh]

    // Stage h[b] (16384 floats = 4096 float4) and W2 (16384 floats)
    {
        const float4* hsrc = reinterpret_cast<const float4*>(g_h + (size_t)b * HID_ * T_);
        const float4* wsrc = reinterpret_cast<const float4*>(W2);
        float4* hdst = reinterpret_cast<float4*>(sh);
        float4* wdst = reinterpret_cast<float4*>(sw2);
#pragma unroll
        for (int i = 0; i < 4; i++) {
            hdst[tid + i * 1024] = hsrc[tid + i * 1024];
            wdst[tid + i * 1024] = wsrc[tid + i * 1024];
        }
    }
    __syncthreads();

    // embds: 256 active threads; thread (eg, t) computes e = 4*eg .. 4*eg+3
    if (tid < 256) {
        int t = tid & 31;
        int eg = tid >> 5;   // 0..7
        float a0 = 0.f, a1 = 0.f, a2 = 0.f, a3 = 0.f;
        const float* w0 = sw2 + (size_t)(4 * eg + 0) * HID_;
        const float* w1 = sw2 + (size_t)(4 * eg + 1) * HID_;
        const float* w2r = sw2 + (size_t)(4 * eg + 2) * HID_;
        const float* w3 = sw2 + (size_t)(4 * eg + 3) * HID_;
#pragma unroll 8
        for (int hh = 0; hh < HID_; hh++) {
            float hv = sh[hh * T_ + t];
            a0 = fmaf(w0[hh], hv, a0);
            a1 = fmaf(w1[hh], hv, a1);
            a2 = fmaf(w2r[hh], hv, a2);
            a3 = fmaf(w3[hh], hv, a3);
        }
        ne[4 * eg + 0][t] = a0 + b2[4 * eg + 0];
        ne[4 * eg + 1][t] = a1 + b2[4 * eg + 1];
        ne[4 * eg + 2][t] = a2 + b2[4 * eg + 2];
        ne[4 * eg + 3][t] = a3 + b2[4 * eg + 3];
    }
    __syncthreads();

    // l2norm over e (axis=1)
    if (tid < T_) {
        float s = 0.0f;
        for (int ee = 0; ee < EMB_; ee++) { float v = ne[ee][tid]; s += v * v; }
        invn[tid] = 1.0f / fmaxf(sqrtf(s), 1e-12f);
    }
    __syncthreads();
    {
        int e = tid >> 5, t = tid & 31;
        ne[e][t] *= invn[t];
    }
    __syncthreads();

    // ns[t] = dot(ne[:,t+1], ne[:,t]), t=0..30
    if (tid < T_ - 1) {
        float s = 0.0f;
        for (int ee = 0; ee < EMB_; ee++) s += ne[ee][tid + 1] * ne[ee][tid];
        nsv[tid] = s;
    }
    __syncthreads();

    // threshold = 3rd smallest of ns (rank 2, tie-break by index)
    if (tid < T_ - 1) {
        float v = nsv[tid];
        int cnt = 0;
        for (int j = 0; j < T_ - 1; j++) {
            float o = nsv[j];
            cnt += (o < v) || (o == v && j < tid);
        }
        if (cnt == 2) thresh = v;
    }
    __syncthreads();

    // groups via cumsum of interval ends
    if (tid == 0) {
        int g = 0;
        grp[0] = 0;
        for (int tt = 1; tt < T_; tt++) {
            g += (nsv[tt - 1] <= thresh) ? 1 : 0;
            grp[tt] = g;
        }
    }
    __syncthreads();

    // centers_sum[e][k], group sizes
    if (tid < EMB_ * NBINS_) {
        int ee = tid >> 2, k = tid & 3;
        float s = 0.0f;
        for (int tt = 0; tt < T_; tt++) if (grp[tt] == k) s += ne[ee][tt];
        csum[ee][k] = s;
    }
    if (tid < NBINS_) {
        float s = 0.0f;
        for (int tt = 0; tt < T_; tt++) s += (grp[tt] == tid) ? 1.0f : 0.0f;
        gsize[tid] = s;
    }
    __syncthreads();

    // normalized centers per bin
    if (tid < NBINS_) {
        int k = tid;
        float gs = gsize[k];
        float inv_gs = (gs > 0.0f) ? (1.0f / gs) : 0.0f;
        float s = 0.0f;
        for (int ee = 0; ee < EMB_; ee++) { float v = csum[ee][k] * inv_gs; s += v * v; }
        float inv_n = 1.0f / fmaxf(sqrtf(s), 1e-12f);
        for (int ee = 0; ee < EMB_; ee++) ncen[ee][k] = csum[ee][k] * inv_gs * inv_n;
    }
    __syncthreads();

    // similarities (scaled)
    if (tid < T_ * NBINS_) {
        int tt = tid >> 2, k = tid & 3;
        float s = 0.0f;
        for (int ee = 0; ee < EMB_; ee++) s += ne[ee][tt] * ncen[ee][k];
        wts[tt][k] = SCALE_ * s;
    }
    __syncthreads();

    // softmax over k per t
    if (tid < T_) {
        float s0 = wts[tid][0], s1 = wts[tid][1], s2 = wts[tid][2], s3 = wts[tid][3];
        float m = fmaxf(fmaxf(s0, s1), fmaxf(s2, s3));
        float e0 = expf(s0 - m), e1 = expf(s1 - m), e2 = expf(s2 - m), e3 = expf(s3 - m);
        float inv = 1.0f / (e0 + e1 + e2 + e3);
        wts[tid][0] = e0 * inv; wts[tid][1] = e1 * inv;
        wts[tid][2] = e2 * inv; wts[tid][3] = e3 * inv;
    }
    __syncthreads();

    // column scales: 1/sum_t weights (or 1 if sum==0)
    if (tid < NBINS_) {
        float s = 0.0f;
        for (int tt = 0; tt < T_; tt++) s += wts[tt][tid];
        sscale[tid] = (s > 0.0f) ? (1.0f / s) : 1.0f;
    }
    __syncthreads();

    if (tid < T_ * NBINS_) {
        int tt = tid >> 2, k = tid & 3;
        g_nw[(size_t)b * T_ * NBINS_ + tt * NBINS_ + k] = wts[tt][k] * sscale[k];
    }
}

// ---------------------------------------------------------------------------
// Kernel 3: out[b,c,k,p] = sum_t x[b,c,t,p] * nw[b,t,k]
// TWO threads per float4 position (lane pairs share the x load -> HW dedup),
// each thread computes 2 bins. 8 accumulator regs/thread -> deep load batching.
// ---------------------------------------------------------------------------
__global__ __launch_bounds__(256)
void output_kernel(const float* __restrict__ x, float* __restrict__ out) {
    __shared__ float swt[B_ * T_ * NBINS_];   // 1024 floats, viewed as float2 pairs
    {
        const float4* src = reinterpret_cast<const float4*>(g_nw);
        reinterpret_cast<float4*>(swt)[threadIdx.x] = src[threadIdx.x];  // 256 float4
    }
    __syncthreads();

    int gt = blockIdx.x * 256 + threadIdx.x;
    const int TOTAL = B_ * C_ * HW4_;
    int idx = gt >> 1;          // float4 position
    int pair = gt & 1;          // bins {0,1} or {2,3}
    if (idx >= TOTAL) return;
    int bc = idx / HW4_;
    int p  = idx - bc * HW4_;
    int b  = bc >> 8;  // /C_

    const float4* xr = reinterpret_cast<const float4*>(x) + (size_t)bc * T_ * HW4_ + p;
    const float2* wb = reinterpret_cast<const float2*>(swt) + b * (T_ * 2) + pair;

    float4 a0 = {0,0,0,0}, a1 = {0,0,0,0};
#pragma unroll
    for (int t = 0; t < T_; t++) {
        float4 v = xr[(size_t)t * HW4_];
        float2 w = wb[2 * t];
        a0.x = fmaf(v.x, w.x, a0.x); a0.y = fmaf(v.y, w.x, a0.y);
        a0.z = fmaf(v.z, w.x, a0.z); a0.w = fmaf(v.w, w.x, a0.w);
        a1.x = fmaf(v.x, w.y, a1.x); a1.y = fmaf(v.y, w.y, a1.y);
        a1.z = fmaf(v.z, w.y, a1.z); a1.w = fmaf(v.w, w.y, a1.w);
    }
    float4* o = reinterpret_cast<float4*>(out)
              + (size_t)bc * NBINS_ * HW4_ + (size_t)pair * 2 * HW4_ + p;
    o[0]    = a0;
    o[HW4_] = a1;
}

// ---------------------------------------------------------------------------
extern "C" void kernel_launch(void* const* d_in, const int* in_sizes, int n_in,
                              void* d_out, int out_size) {
    const float* x  = (const float*)d_in[0];
    const float* W1 = (const float*)d_in[1];
    const float* b1 = (const float*)d_in[2];
    const float* W2 = (const float*)d_in[3];
    const float* b2 = (const float*)d_in[4];
    float* out = (float*)d_out;

    // Allow 128 KB dynamic smem for weights_kernel (host-side attr, capture-safe)
    static int attr_done = 0;
    if (!attr_done) {
        cudaFuncSetAttribute(weights_kernel,
                             cudaFuncAttributeMaxDynamicSharedMemorySize,
                             (HID_ * T_ + EMB_ * HID_) * (int)sizeof(float));
        attr_done = 1;
    }

    pool_kernel<<<(B_ * C_ * T_) / 8, 256>>>(x);
    mlp1_kernel<<<(B_ * HID_) / 8, 256>>>(W1, b1);
    weights_kernel<<<B_, 1024, (HID_ * T_ + EMB_ * HID_) * sizeof(float)>>>(W2, b2);
    int total2 = B_ * C_ * HW4_ * 2;
    output_kernel<<<total2 / 256, 256>>>(x, out);
}

// round 4
// speedup vs baseline: 1.5911x; 1.1997x over previous
#include <cuda_runtime.h>
#include <cuda_bf16.h>
#include <math.h>

// Problem constants
#define B_  8
#define C_  256
#define T_  32
#define HW_ 784            // 28*28
#define HW4_ 196           // HW/4
#define HID_ 512
#define EMB_ 32
#define NBINS_ 4
#define SCALE_ 5.0f

// Scratch (device globals — no allocation allowed)
__device__ float g_pooled[B_ * C_ * T_];   // [B,C,T]
__device__ float g_h[B_ * HID_ * T_];      // [B,HID,T]
__device__ float g_nw[B_ * T_ * NBINS_];   // [B,T,4] => float4 per (b,t)

// ---------------------------------------------------------------------------
// Kernel 1: spatial mean pool.  One warp per (b,c,t) row of 784 floats.
// Processes batches in ascending order (bid order) so batches ~3..7 remain
// L2-resident when the output pass starts.
// ---------------------------------------------------------------------------
__global__ void pool_kernel(const float* __restrict__ x) {
    int warp = (blockIdx.x * blockDim.x + threadIdx.x) >> 5;
    int lane = threadIdx.x & 31;
    if (warp >= B_ * C_ * T_) return;
    const float4* row = reinterpret_cast<const float4*>(x) + (size_t)warp * HW4_;
    float4 v0 = row[lane];
    float4 v1 = row[lane + 32];
    float4 v2 = row[lane + 64];
    float4 v3 = row[lane + 96];
    float4 v4 = row[lane + 128];
    float4 v5 = row[lane + 160];
    float4 v6 = (lane < 4) ? row[lane + 192] : make_float4(0.f, 0.f, 0.f, 0.f);
    float s = (v0.x + v0.y) + (v0.z + v0.w);
    s += (v1.x + v1.y) + (v1.z + v1.w);
    s += (v2.x + v2.y) + (v2.z + v2.w);
    s += (v3.x + v3.y) + (v3.z + v3.w);
    s += (v4.x + v4.y) + (v4.z + v4.w);
    s += (v5.x + v5.y) + (v5.z + v5.w);
    s += (v6.x + v6.y) + (v6.z + v6.w);
#pragma unroll
    for (int o = 16; o > 0; o >>= 1) s += __shfl_xor_sync(0xFFFFFFFFu, s, o);
    if (lane == 0) g_pooled[warp] = s * (1.0f / (float)HW_);
}

// ---------------------------------------------------------------------------
// Kernel 2a: h = hswish(W1 @ pooled + b1).
// Block = 256 threads = 8 warps, one b per block, 8 hids per block.
// pooled[b] (32 KB) AND 8 W1 rows (8 KB) staged in shared.
// ---------------------------------------------------------------------------
__global__ __launch_bounds__(256)
void mlp1_kernel(const float* __restrict__ W1, const float* __restrict__ b1) {
    __shared__ float sp[C_ * T_];   // 32 KB
    __shared__ float sw[8 * C_];    // 8 KB
    int b = blockIdx.x >> 6;                 // /64
    int hid0 = (blockIdx.x & 63) * 8;
    int tid = threadIdx.x;
    {
        const float4* src = reinterpret_cast<const float4*>(g_pooled + (size_t)b * C_ * T_);
        float4* dst = reinterpret_cast<float4*>(sp);
#pragma unroll
        for (int i = 0; i < 8; i++) dst[tid + i * 256] = src[tid + i * 256];
    }
    {
        const float4* src = reinterpret_cast<const float4*>(W1 + (size_t)hid0 * C_);
        float4* dst = reinterpret_cast<float4*>(sw);
        dst[tid] = src[tid];
        dst[tid + 256] = src[tid + 256];
    }
    __syncthreads();

    int w = tid >> 5;        // warp -> hid offset
    int lane = tid & 31;     // t
    int hid = hid0 + w;
    const float* wr = sw + w * C_;
    float a0 = 0.f, a1 = 0.f, a2 = 0.f, a3 = 0.f;
#pragma unroll 8
    for (int c = 0; c < C_; c += 4) {
        a0 = fmaf(wr[c + 0], sp[(c + 0) * T_ + lane], a0);
        a1 = fmaf(wr[c + 1], sp[(c + 1) * T_ + lane], a1);
        a2 = fmaf(wr[c + 2], sp[(c + 2) * T_ + lane], a2);
        a3 = fmaf(wr[c + 3], sp[(c + 3) * T_ + lane], a3);
    }
    float acc = ((a0 + a1) + (a2 + a3)) + b1[hid];
    float g = fminf(fmaxf(acc + 3.0f, 0.0f), 6.0f);
    acc = acc * g * (1.0f / 6.0f);
    g_h[((size_t)b * HID_ + hid) * T_ + lane] = acc;
}

// ---------------------------------------------------------------------------
// Kernel 2b: per-batch block (1024 threads). h[b] + W2 staged in 128 KB smem,
// embds with 4-e register tiling, then grouping/softmax.
// ---------------------------------------------------------------------------
extern __shared__ float dynsm[];   // [0:16384)=h [hid][t], [16384:32768)=W2 [e][hh]

__global__ __launch_bounds__(1024, 1)
void weights_kernel(const float* __restrict__ W2, const float* __restrict__ b2) {
    __shared__ float ne[EMB_][T_ + 1];
    __shared__ float invn[T_];
    __shared__ float nsv[T_];
    __shared__ float thresh;
    __shared__ int   grp[T_];
    __shared__ float csum[EMB_][NBINS_];
    __shared__ float gsize[NBINS_];
    __shared__ float ncen[EMB_][NBINS_];
    __shared__ float wts[T_][NBINS_];
    __shared__ float sscale[NBINS_];

    int b = blockIdx.x;
    int tid = threadIdx.x;
    float* sh  = dynsm;
    float* sw2 = dynsm + HID_ * T_;

    {
        const float4* hsrc = reinterpret_cast<const float4*>(g_h + (size_t)b * HID_ * T_);
        const float4* wsrc = reinterpret_cast<const float4*>(W2);
        float4* hdst = reinterpret_cast<float4*>(sh);
        float4* wdst = reinterpret_cast<float4*>(sw2);
#pragma unroll
        for (int i = 0; i < 4; i++) {
            hdst[tid + i * 1024] = hsrc[tid + i * 1024];
            wdst[tid + i * 1024] = wsrc[tid + i * 1024];
        }
    }
    __syncthreads();

    if (tid < 256) {
        int t = tid & 31;
        int eg = tid >> 5;   // 0..7
        float a0 = 0.f, a1 = 0.f, a2 = 0.f, a3 = 0.f;
        const float* w0 = sw2 + (size_t)(4 * eg + 0) * HID_;
        const float* w1 = sw2 + (size_t)(4 * eg + 1) * HID_;
        const float* w2r = sw2 + (size_t)(4 * eg + 2) * HID_;
        const float* w3 = sw2 + (size_t)(4 * eg + 3) * HID_;
#pragma unroll 8
        for (int hh = 0; hh < HID_; hh++) {
            float hv = sh[hh * T_ + t];
            a0 = fmaf(w0[hh], hv, a0);
            a1 = fmaf(w1[hh], hv, a1);
            a2 = fmaf(w2r[hh], hv, a2);
            a3 = fmaf(w3[hh], hv, a3);
        }
        ne[4 * eg + 0][t] = a0 + b2[4 * eg + 0];
        ne[4 * eg + 1][t] = a1 + b2[4 * eg + 1];
        ne[4 * eg + 2][t] = a2 + b2[4 * eg + 2];
        ne[4 * eg + 3][t] = a3 + b2[4 * eg + 3];
    }
    __syncthreads();

    if (tid < T_) {
        float s = 0.0f;
        for (int ee = 0; ee < EMB_; ee++) { float v = ne[ee][tid]; s += v * v; }
        invn[tid] = 1.0f / fmaxf(sqrtf(s), 1e-12f);
    }
    __syncthreads();
    {
        int e = tid >> 5, t = tid & 31;
        ne[e][t] *= invn[t];
    }
    __syncthreads();

    if (tid < T_ - 1) {
        float s = 0.0f;
        for (int ee = 0; ee < EMB_; ee++) s += ne[ee][tid + 1] * ne[ee][tid];
        nsv[tid] = s;
    }
    __syncthreads();

    if (tid < T_ - 1) {
        float v = nsv[tid];
        int cnt = 0;
        for (int j = 0; j < T_ - 1; j++) {
            float o = nsv[j];
            cnt += (o < v) || (o == v && j < tid);
        }
        if (cnt == 2) thresh = v;
    }
    __syncthreads();

    if (tid == 0) {
        int g = 0;
        grp[0] = 0;
        for (int tt = 1; tt < T_; tt++) {
            g += (nsv[tt - 1] <= thresh) ? 1 : 0;
            grp[tt] = g;
        }
    }
    __syncthreads();

    if (tid < EMB_ * NBINS_) {
        int ee = tid >> 2, k = tid & 3;
        float s = 0.0f;
        for (int tt = 0; tt < T_; tt++) if (grp[tt] == k) s += ne[ee][tt];
        csum[ee][k] = s;
    }
    if (tid < NBINS_) {
        float s = 0.0f;
        for (int tt = 0; tt < T_; tt++) s += (grp[tt] == tid) ? 1.0f : 0.0f;
        gsize[tid] = s;
    }
    __syncthreads();

    if (tid < NBINS_) {
        int k = tid;
        float gs = gsize[k];
        float inv_gs = (gs > 0.0f) ? (1.0f / gs) : 0.0f;
        float s = 0.0f;
        for (int ee = 0; ee < EMB_; ee++) { float v = csum[ee][k] * inv_gs; s += v * v; }
        float inv_n = 1.0f / fmaxf(sqrtf(s), 1e-12f);
        for (int ee = 0; ee < EMB_; ee++) ncen[ee][k] = csum[ee][k] * inv_gs * inv_n;
    }
    __syncthreads();

    if (tid < T_ * NBINS_) {
        int tt = tid >> 2, k = tid & 3;
        float s = 0.0f;
        for (int ee = 0; ee < EMB_; ee++) s += ne[ee][tt] * ncen[ee][k];
        wts[tt][k] = SCALE_ * s;
    }
    __syncthreads();

    if (tid < T_) {
        float s0 = wts[tid][0], s1 = wts[tid][1], s2 = wts[tid][2], s3 = wts[tid][3];
        float m = fmaxf(fmaxf(s0, s1), fmaxf(s2, s3));
        float e0 = expf(s0 - m), e1 = expf(s1 - m), e2 = expf(s2 - m), e3 = expf(s3 - m);
        float inv = 1.0f / (e0 + e1 + e2 + e3);
        wts[tid][0] = e0 * inv; wts[tid][1] = e1 * inv;
        wts[tid][2] = e2 * inv; wts[tid][3] = e3 * inv;
    }
    __syncthreads();

    if (tid < NBINS_) {
        float s = 0.0f;
        for (int tt = 0; tt < T_; tt++) s += wts[tt][tid];
        sscale[tid] = (s > 0.0f) ? (1.0f / s) : 1.0f;
    }
    __syncthreads();

    if (tid < T_ * NBINS_) {
        int tt = tid >> 2, k = tid & 3;
        g_nw[(size_t)b * T_ * NBINS_ + tt * NBINS_ + k] = wts[tt][k] * sscale[k];
    }
}

// ---------------------------------------------------------------------------
// Kernel 3 (R2 formulation + L2-residency phasing):
// out[b,c,k,p] = sum_t x[b,c,t,p] * nw[b,t,k]
// One thread per (b,c,p4); all 4 bins. bc order REVERSED so the
// most-recently-pooled batches (still L2-resident) are consumed first.
// __ldcs on x (last use, evict-first) / __stcs on out (streaming writes).
// ---------------------------------------------------------------------------
__global__ __launch_bounds__(256, 4)
void output_kernel(const float* __restrict__ x, float* __restrict__ out) {
    __shared__ float4 swt[B_ * T_];   // [b][t]
    {
        const float4* src = reinterpret_cast<const float4*>(g_nw);
        swt[threadIdx.x] = src[threadIdx.x];   // 256 threads, 256 entries
    }
    __syncthreads();

    int gtid = blockIdx.x * blockDim.x + threadIdx.x;
    const int TOTAL = B_ * C_ * HW4_;
    if (gtid >= TOTAL) return;
    int bc = gtid / HW4_;
    int p  = gtid - bc * HW4_;
    bc = (B_ * C_ - 1) - bc;          // reversed: batch 7 first (L2-resident)
    int b  = bc >> 8;  // /C_

    const float4* xr = reinterpret_cast<const float4*>(x) + (size_t)bc * T_ * HW4_ + p;
    const float4* wb = swt + b * T_;

    float4 a0 = {0,0,0,0}, a1 = {0,0,0,0}, a2 = {0,0,0,0}, a3 = {0,0,0,0};
#pragma unroll
    for (int t = 0; t < T_; t++) {
        float4 v = __ldcs(&xr[(size_t)t * HW4_]);
        float4 w = wb[t];
        a0.x = fmaf(v.x, w.x, a0.x); a0.y = fmaf(v.y, w.x, a0.y);
        a0.z = fmaf(v.z, w.x, a0.z); a0.w = fmaf(v.w, w.x, a0.w);
        a1.x = fmaf(v.x, w.y, a1.x); a1.y = fmaf(v.y, w.y, a1.y);
        a1.z = fmaf(v.z, w.y, a1.z); a1.w = fmaf(v.w, w.y, a1.w);
        a2.x = fmaf(v.x, w.z, a2.x); a2.y = fmaf(v.y, w.z, a2.y);
        a2.z = fmaf(v.z, w.z, a2.z); a2.w = fmaf(v.w, w.z, a2.w);
        a3.x = fmaf(v.x, w.w, a3.x); a3.y = fmaf(v.y, w.w, a3.y);
        a3.z = fmaf(v.z, w.w, a3.z); a3.w = fmaf(v.w, w.w, a3.w);
    }
    float4* o = reinterpret_cast<float4*>(out) + (size_t)bc * NBINS_ * HW4_ + p;
    __stcs(&o[0 * HW4_], a0);
    __stcs(&o[1 * HW4_], a1);
    __stcs(&o[2 * HW4_], a2);
    __stcs(&o[3 * HW4_], a3);
}

// ---------------------------------------------------------------------------
extern "C" void kernel_launch(void* const* d_in, const int* in_sizes, int n_in,
                              void* d_out, int out_size) {
    const float* x  = (const float*)d_in[0];
    const float* W1 = (const float*)d_in[1];
    const float* b1 = (const float*)d_in[2];
    const float* W2 = (const float*)d_in[3];
    const float* b2 = (const float*)d_in[4];
    float* out = (float*)d_out;

    static int attr_done = 0;
    if (!attr_done) {
        cudaFuncSetAttribute(weights_kernel,
                             cudaFuncAttributeMaxDynamicSharedMemorySize,
                             (HID_ * T_ + EMB_ * HID_) * (int)sizeof(float));
        attr_done = 1;
    }

    pool_kernel<<<(B_ * C_ * T_) / 8, 256>>>(x);
    mlp1_kernel<<<(B_ * HID_) / 8, 256>>>(W1, b1);
    weights_kernel<<<B_, 1024, (HID_ * T_ + EMB_ * HID_) * sizeof(float)>>>(W2, b2);
    int total = B_ * C_ * HW4_;
    output_kernel<<<(total + 255) / 256, 256>>>(x, out);
}